// round 3
// baseline (speedup 1.0000x reference)
#include <cuda_runtime.h>
#include <math.h>

// ---------------- problem dims ----------------
#define Bn    8
#define Sq    1024
#define Cdim  640
#define Tctx  77
#define CTXD  768
#define NHEAD 8
#define HSZ   80
#define FFD   5120
#define FFH   2560
#define Mrows (Bn * Sq)      // 8192
#define MCTX  (Bn * Tctx)    // 616

// ---------------- scratch (static device, no allocs allowed) ----------------
__device__ float g_ln  [(size_t)Mrows * Cdim];
__device__ float g_y   [(size_t)Mrows * Cdim];
__device__ float g_q   [(size_t)Mrows * Cdim];
__device__ float g_k   [(size_t)Mrows * Cdim];
__device__ float g_v   [(size_t)Mrows * Cdim];
__device__ float g_at  [(size_t)Mrows * Cdim];
__device__ float g_t   [(size_t)Mrows * Cdim];
__device__ float g_sc  [(size_t)64 * 1024 * 1024];   // scores: 64 bh x 1024 x 1024
__device__ float g_ff  [(size_t)Mrows * FFD];
__device__ float g_gg  [(size_t)Mrows * FFH];

// ---------------- GroupNorm: 32 groups of 20 ch, reduce over 1024*20 ----------------
__global__ void groupnorm_kernel(const float* __restrict__ x,
                                 const float* __restrict__ gamma,
                                 const float* __restrict__ beta,
                                 float* __restrict__ out)
{
    const int b = blockIdx.x >> 5;
    const int g = blockIdx.x & 31;
    const float* base = x + (size_t)b * Sq * Cdim + g * 20;
    float sum = 0.f, sq = 0.f;
    for (int idx = threadIdx.x; idx < Sq * 20; idx += 256) {
        int hw = idx / 20, c = idx % 20;
        float v = base[(size_t)hw * Cdim + c];
        sum += v; sq += v * v;
    }
    #pragma unroll
    for (int o = 16; o > 0; o >>= 1) {
        sum += __shfl_xor_sync(0xffffffffu, sum, o);
        sq  += __shfl_xor_sync(0xffffffffu, sq,  o);
    }
    __shared__ float s1[8], s2[8];
    const int wid = threadIdx.x >> 5, lane = threadIdx.x & 31;
    if (lane == 0) { s1[wid] = sum; s2[wid] = sq; }
    __syncthreads();
    float tot = 0.f, totq = 0.f;
    #pragma unroll
    for (int i = 0; i < 8; i++) { tot += s1[i]; totq += s2[i]; }
    const float mean = tot * (1.f / 20480.f);
    const float var  = totq * (1.f / 20480.f) - mean * mean;
    const float rstd = rsqrtf(var + 1e-5f);
    float* ob = out + (size_t)b * Sq * Cdim + g * 20;
    for (int idx = threadIdx.x; idx < Sq * 20; idx += 256) {
        int hw = idx / 20, c = idx % 20;
        float v = base[(size_t)hw * Cdim + c];
        ob[(size_t)hw * Cdim + c] = (v - mean) * rstd * gamma[g * 20 + c] + beta[g * 20 + c];
    }
}

// ---------------- LayerNorm (640): warp per row, vectorized ----------------
__global__ void layernorm_kernel(const float* __restrict__ x,
                                 const float* __restrict__ g,
                                 const float* __restrict__ b,
                                 float* __restrict__ out, int rows)
{
    const int w = (blockIdx.x << 3) + (threadIdx.x >> 5);
    if (w >= rows) return;
    const int lane = threadIdx.x & 31;
    const float* row = x + (size_t)w * Cdim;
    float4 v[5];
    float sum = 0.f, sq = 0.f;
    #pragma unroll
    for (int p = 0; p < 5; p++) {
        v[p] = *reinterpret_cast<const float4*>(row + (lane + 32 * p) * 4);
        sum += v[p].x + v[p].y + v[p].z + v[p].w;
        sq  += v[p].x * v[p].x + v[p].y * v[p].y + v[p].z * v[p].z + v[p].w * v[p].w;
    }
    #pragma unroll
    for (int o = 16; o > 0; o >>= 1) {
        sum += __shfl_xor_sync(0xffffffffu, sum, o);
        sq  += __shfl_xor_sync(0xffffffffu, sq,  o);
    }
    const float mean = sum * (1.f / 640.f);
    const float var  = sq * (1.f / 640.f) - mean * mean;
    const float rstd = rsqrtf(var + 1e-5f);
    float* orow = out + (size_t)w * Cdim;
    #pragma unroll
    for (int p = 0; p < 5; p++) {
        const int off = (lane + 32 * p) * 4;
        const float4 g4 = *reinterpret_cast<const float4*>(g + off);
        const float4 b4 = *reinterpret_cast<const float4*>(b + off);
        float4 o;
        o.x = (v[p].x - mean) * rstd * g4.x + b4.x;
        o.y = (v[p].y - mean) * rstd * g4.y + b4.y;
        o.z = (v[p].z - mean) * rstd * g4.z + b4.z;
        o.w = (v[p].w - mean) * rstd * g4.w + b4.w;
        *reinterpret_cast<float4*>(orow + off) = o;
    }
}

// ---------------- SGEMM: C[M,N] = A[M,K] @ B[K,N] (+bias)(+residual) ----------------
// 128x128 tile, BK=8, 256 threads, 8x8 per thread.
__global__ __launch_bounds__(256)
void sgemm_kernel(const float* __restrict__ A, const float* __restrict__ B,
                  const float* __restrict__ bias, const float* __restrict__ Res,
                  float* __restrict__ C, int M, int N, int K)
{
    __shared__ float As[8][128];
    __shared__ float Bs[8][128];
    const int tid = threadIdx.x;
    const int tx = tid & 15, ty = tid >> 4;
    const int row0 = blockIdx.y * 128, col0 = blockIdx.x * 128;
    float acc[8][8];
    #pragma unroll
    for (int i = 0; i < 8; i++)
        #pragma unroll
        for (int j = 0; j < 8; j++) acc[i][j] = 0.f;

    const int a_r = tid >> 1, a_c = (tid & 1) * 4;   // 128 rows x 8 cols
    const int b_r = tid >> 5, b_c = (tid & 31) * 4;  // 8 rows x 128 cols

    for (int k0 = 0; k0 < K; k0 += 8) {
        float4 av = make_float4(0.f, 0.f, 0.f, 0.f);
        const int ar = row0 + a_r;
        if (ar < M) av = *reinterpret_cast<const float4*>(A + (size_t)ar * K + k0 + a_c);
        As[a_c + 0][a_r] = av.x; As[a_c + 1][a_r] = av.y;
        As[a_c + 2][a_r] = av.z; As[a_c + 3][a_r] = av.w;
        const float4 bv = *reinterpret_cast<const float4*>(B + (size_t)(k0 + b_r) * N + col0 + b_c);
        *reinterpret_cast<float4*>(&Bs[b_r][b_c]) = bv;
        __syncthreads();
        #pragma unroll
        for (int k = 0; k < 8; k++) {
            const float4 a0 = *reinterpret_cast<const float4*>(&As[k][ty * 8]);
            const float4 a1 = *reinterpret_cast<const float4*>(&As[k][ty * 8 + 4]);
            const float4 b0 = *reinterpret_cast<const float4*>(&Bs[k][tx * 8]);
            const float4 b1 = *reinterpret_cast<const float4*>(&Bs[k][tx * 8 + 4]);
            const float af[8] = {a0.x, a0.y, a0.z, a0.w, a1.x, a1.y, a1.z, a1.w};
            const float bf[8] = {b0.x, b0.y, b0.z, b0.w, b1.x, b1.y, b1.z, b1.w};
            #pragma unroll
            for (int i = 0; i < 8; i++)
                #pragma unroll
                for (int j = 0; j < 8; j++) acc[i][j] += af[i] * bf[j];
        }
        __syncthreads();
    }

    #pragma unroll
    for (int i = 0; i < 8; i++) {
        const int r = row0 + ty * 8 + i;
        if (r >= M) continue;
        #pragma unroll
        for (int jj = 0; jj < 2; jj++) {
            const int c = col0 + tx * 8 + jj * 4;
            float4 v = make_float4(acc[i][jj * 4 + 0], acc[i][jj * 4 + 1],
                                   acc[i][jj * 4 + 2], acc[i][jj * 4 + 3]);
            if (bias) {
                const float4 bb = *reinterpret_cast<const float4*>(bias + c);
                v.x += bb.x; v.y += bb.y; v.z += bb.z; v.w += bb.w;
            }
            if (Res) {
                const float4 rv = *reinterpret_cast<const float4*>(Res + (size_t)r * N + c);
                v.x += rv.x; v.y += rv.y; v.z += rv.z; v.w += rv.w;
            }
            *reinterpret_cast<float4*>(C + (size_t)r * N + c) = v;
        }
    }
}

// ---------------- attention scores: S[bh, i, j] = scale * Q_i . K_j ----------------
// Q,K layouts: [B, seq, NHEAD, HSZ] flattened rows of 640. 64x64 tiles.
__global__ __launch_bounds__(256)
void attn_scores_kernel(const float* __restrict__ Q, const float* __restrict__ Kb,
                        float* __restrict__ Sout, int Tk, int kSeq)
{
    const int bh = blockIdx.z, b = bh >> 3, n = bh & 7;
    const float* qb = Q + (size_t)b * Sq * Cdim + n * HSZ;
    const float* kb = Kb + (size_t)b * kSeq * Cdim + n * HSZ;
    float* sb = Sout + (size_t)bh * Sq * Tk;
    const int i0 = blockIdx.y * 64, j0 = blockIdx.x * 64;
    __shared__ float Qs[16][64], Ks[16][64];
    const int tid = threadIdx.x, tx = tid & 15, ty = tid >> 4;
    const int lr = tid >> 2, lc = (tid & 3) * 4;
    float acc[4][4] = {};
    for (int kk = 0; kk < HSZ; kk += 16) {
        const float4 qv = *reinterpret_cast<const float4*>(qb + (size_t)(i0 + lr) * Cdim + kk + lc);
        Qs[lc + 0][lr] = qv.x; Qs[lc + 1][lr] = qv.y; Qs[lc + 2][lr] = qv.z; Qs[lc + 3][lr] = qv.w;
        float4 kv = make_float4(0.f, 0.f, 0.f, 0.f);
        if (j0 + lr < Tk) kv = *reinterpret_cast<const float4*>(kb + (size_t)(j0 + lr) * Cdim + kk + lc);
        Ks[lc + 0][lr] = kv.x; Ks[lc + 1][lr] = kv.y; Ks[lc + 2][lr] = kv.z; Ks[lc + 3][lr] = kv.w;
        __syncthreads();
        #pragma unroll
        for (int k = 0; k < 16; k++) {
            const float4 a = *reinterpret_cast<const float4*>(&Qs[k][ty * 4]);
            const float4 bb = *reinterpret_cast<const float4*>(&Ks[k][tx * 4]);
            const float af[4] = {a.x, a.y, a.z, a.w};
            const float bf[4] = {bb.x, bb.y, bb.z, bb.w};
            #pragma unroll
            for (int i = 0; i < 4; i++)
                #pragma unroll
                for (int j = 0; j < 4; j++) acc[i][j] += af[i] * bf[j];
        }
        __syncthreads();
    }
    const float scale = 0.11180339887498949f; // 80^-0.5
    #pragma unroll
    for (int i = 0; i < 4; i++) {
        const int r = i0 + ty * 4 + i;
        #pragma unroll
        for (int j = 0; j < 4; j++) {
            const int c = j0 + tx * 4 + j;
            if (c < Tk) sb[(size_t)r * Tk + c] = acc[i][j] * scale;
        }
    }
}

// ---------------- softmax (warp per row, L <= 1024) ----------------
__global__ void softmax_kernel(float* __restrict__ S, int rows, int L)
{
    const int w = (blockIdx.x << 3) + (threadIdx.x >> 5);
    if (w >= rows) return;
    const int lane = threadIdx.x & 31;
    float* row = S + (size_t)w * L;
    float v[32];
    float m = -3.4e38f;
    #pragma unroll
    for (int p = 0; p < 32; p++) {
        const int i = lane + (p << 5);
        v[p] = (i < L) ? row[i] : -3.4e38f;
        m = fmaxf(m, v[p]);
    }
    #pragma unroll
    for (int o = 16; o > 0; o >>= 1) m = fmaxf(m, __shfl_xor_sync(0xffffffffu, m, o));
    float s = 0.f;
    #pragma unroll
    for (int p = 0; p < 32; p++) {
        const int i = lane + (p << 5);
        if (i < L) { v[p] = __expf(v[p] - m); s += v[p]; }
    }
    #pragma unroll
    for (int o = 16; o > 0; o >>= 1) s += __shfl_xor_sync(0xffffffffu, s, o);
    const float inv = 1.f / s;
    #pragma unroll
    for (int p = 0; p < 32; p++) {
        const int i = lane + (p << 5);
        if (i < L) row[i] = v[p] * inv;
    }
}

// ---------------- attn output: O[bh, i, :] = P[bh, i, :] @ V ----------------
__global__ __launch_bounds__(256)
void attn_pv_kernel(const float* __restrict__ P, const float* __restrict__ V,
                    float* __restrict__ O, int Tk, int vSeq)
{
    const int bh = blockIdx.z, b = bh >> 3, n = bh & 7;
    const float* pb = P + (size_t)bh * Sq * Tk;
    const float* vb = V + (size_t)b * vSeq * Cdim + n * HSZ;
    float* ob = O + (size_t)b * Sq * Cdim + n * HSZ;
    const int i0 = blockIdx.x * 64;
    __shared__ float Ps[16][64];
    __shared__ float Vs[16][80];
    const int tid = threadIdx.x, tx = tid & 15, ty = tid >> 4;
    const int lr = tid >> 2, lc = (tid & 3) * 4;
    float acc[4][5] = {};
    for (int t0 = 0; t0 < Tk; t0 += 16) {
        #pragma unroll
        for (int l = 0; l < 4; l++) {
            const int t = t0 + lc + l;
            Ps[lc + l][lr] = (t < Tk) ? pb[(size_t)(i0 + lr) * Tk + t] : 0.f;
        }
        for (int e = tid; e < 16 * 80; e += 256) {
            const int tr = e / 80, c = e % 80;
            Vs[tr][c] = (t0 + tr < Tk) ? vb[(size_t)(t0 + tr) * Cdim + c] : 0.f;
        }
        __syncthreads();
        #pragma unroll
        for (int k = 0; k < 16; k++) {
            const float p0 = Ps[k][ty * 4 + 0], p1 = Ps[k][ty * 4 + 1];
            const float p2 = Ps[k][ty * 4 + 2], p3 = Ps[k][ty * 4 + 3];
            #pragma unroll
            for (int j = 0; j < 5; j++) {
                const float vv = Vs[k][tx + 16 * j];
                acc[0][j] += p0 * vv; acc[1][j] += p1 * vv;
                acc[2][j] += p2 * vv; acc[3][j] += p3 * vv;
            }
        }
        __syncthreads();
    }
    #pragma unroll
    for (int i = 0; i < 4; i++) {
        const int r = i0 + ty * 4 + i;
        #pragma unroll
        for (int j = 0; j < 5; j++)
            ob[(size_t)r * Cdim + tx + 16 * j] = acc[i][j];
    }
}

// ---------------- GEGLU ----------------
__device__ __forceinline__ float geglu_one(float xh, float g)
{
    const float t = tanhf(g * 0.7978845608f * (1.f + 0.044715f * g * g));
    return xh * 0.5f * g * (1.f + t);
}

__global__ void geglu_kernel(const float* __restrict__ ff, float* __restrict__ out)
{
    const size_t idx = (size_t)blockIdx.x * blockDim.x + threadIdx.x; // float4 index
    if (idx >= (size_t)Mrows * (FFH / 4)) return;
    const size_t row = idx / (FFH / 4);
    const int c4 = (int)(idx % (FFH / 4));
    const float4 xh = *reinterpret_cast<const float4*>(ff + row * FFD + c4 * 4);
    const float4 gt = *reinterpret_cast<const float4*>(ff + row * FFD + FFH + c4 * 4);
    float4 o;
    o.x = geglu_one(xh.x, gt.x);
    o.y = geglu_one(xh.y, gt.y);
    o.z = geglu_one(xh.z, gt.z);
    o.w = geglu_one(xh.w, gt.w);
    *reinterpret_cast<float4*>(out + row * FFH + c4 * 4) = o;
}

// ---------------- host orchestration ----------------
extern "C" void kernel_launch(void* const* d_in, const int* in_sizes, int n_in,
                              void* d_out, int out_size)
{
    (void)in_sizes; (void)n_in; (void)out_size;
    const float* x     = (const float*)d_in[0];
    const float* ctx   = (const float*)d_in[1];
    const float* gn_g  = (const float*)d_in[2];
    const float* gn_b  = (const float*)d_in[3];
    const float* piw   = (const float*)d_in[4];
    const float* pib   = (const float*)d_in[5];
    const float* ln1g  = (const float*)d_in[6];
    const float* ln1b  = (const float*)d_in[7];
    const float* a1q   = (const float*)d_in[8];
    const float* a1k   = (const float*)d_in[9];
    const float* a1v   = (const float*)d_in[10];
    const float* a1o   = (const float*)d_in[11];
    const float* a1ob  = (const float*)d_in[12];
    const float* ln2g  = (const float*)d_in[13];
    const float* ln2b  = (const float*)d_in[14];
    const float* a2q   = (const float*)d_in[15];
    const float* a2k   = (const float*)d_in[16];
    const float* a2v   = (const float*)d_in[17];
    const float* a2o   = (const float*)d_in[18];
    const float* a2ob  = (const float*)d_in[19];
    const float* ln3g  = (const float*)d_in[20];
    const float* ln3b  = (const float*)d_in[21];
    const float* ff1w  = (const float*)d_in[22];
    const float* ff1b  = (const float*)d_in[23];
    const float* ff2w  = (const float*)d_in[24];
    const float* ff2b  = (const float*)d_in[25];
    const float* prw   = (const float*)d_in[26];
    const float* prb   = (const float*)d_in[27];
    float* out = (float*)d_out;

    float *ln, *y, *q, *k, *v, *at, *t, *sc, *ff, *gg;
    cudaGetSymbolAddress((void**)&ln, g_ln);
    cudaGetSymbolAddress((void**)&y,  g_y);
    cudaGetSymbolAddress((void**)&q,  g_q);
    cudaGetSymbolAddress((void**)&k,  g_k);
    cudaGetSymbolAddress((void**)&v,  g_v);
    cudaGetSymbolAddress((void**)&at, g_at);
    cudaGetSymbolAddress((void**)&t,  g_t);
    cudaGetSymbolAddress((void**)&sc, g_sc);
    cudaGetSymbolAddress((void**)&ff, g_ff);
    cudaGetSymbolAddress((void**)&gg, g_gg);

    const dim3 gemm640(Cdim / 128, Mrows / 128);        // (5, 64)
    const dim3 gemmCtx(Cdim / 128, (MCTX + 127) / 128); // (5, 5)
    const dim3 gemmFF(FFD / 128, Mrows / 128);          // (40, 64)

    // y = proj_in(group_norm(x))
    groupnorm_kernel<<<Bn * 32, 256>>>(x, gn_g, gn_b, ln);
    sgemm_kernel<<<gemm640, 256>>>(ln, piw, pib, nullptr, y, Mrows, Cdim, Cdim);

    // self attention
    layernorm_kernel<<<Mrows / 8, 256>>>(y, ln1g, ln1b, ln, Mrows);
    sgemm_kernel<<<gemm640, 256>>>(ln, a1q, nullptr, nullptr, q, Mrows, Cdim, Cdim);
    sgemm_kernel<<<gemm640, 256>>>(ln, a1k, nullptr, nullptr, k, Mrows, Cdim, Cdim);
    sgemm_kernel<<<gemm640, 256>>>(ln, a1v, nullptr, nullptr, v, Mrows, Cdim, Cdim);
    attn_scores_kernel<<<dim3(16, 16, 64), 256>>>(q, k, sc, Sq, Sq);
    softmax_kernel<<<(64 * Sq) / 8, 256>>>(sc, 64 * Sq, Sq);
    attn_pv_kernel<<<dim3(16, 1, 64), 256>>>(sc, v, at, Sq, Sq);
    sgemm_kernel<<<gemm640, 256>>>(at, a1o, a1ob, y, t, Mrows, Cdim, Cdim);

    // cross attention
    layernorm_kernel<<<Mrows / 8, 256>>>(t, ln2g, ln2b, ln, Mrows);
    sgemm_kernel<<<gemmCtx, 256>>>(ctx, a2k, nullptr, nullptr, k, MCTX, Cdim, CTXD);
    sgemm_kernel<<<gemmCtx, 256>>>(ctx, a2v, nullptr, nullptr, v, MCTX, Cdim, CTXD);
    sgemm_kernel<<<gemm640, 256>>>(ln, a2q, nullptr, nullptr, q, Mrows, Cdim, Cdim);
    attn_scores_kernel<<<dim3(2, 16, 64), 256>>>(q, k, sc, Tctx, Tctx);
    softmax_kernel<<<(64 * Sq) / 8, 256>>>(sc, 64 * Sq, Tctx);
    attn_pv_kernel<<<dim3(16, 1, 64), 256>>>(sc, v, at, Tctx, Tctx);
    sgemm_kernel<<<gemm640, 256>>>(at, a2o, a2ob, t, t, Mrows, Cdim, Cdim);

    // GEGLU feed-forward
    layernorm_kernel<<<Mrows / 8, 256>>>(t, ln3g, ln3b, ln, Mrows);
    sgemm_kernel<<<gemmFF, 256>>>(ln, ff1w, ff1b, nullptr, ff, Mrows, FFD, Cdim);
    geglu_kernel<<<(Mrows * (FFH / 4)) / 256, 256>>>(ff, gg);
    sgemm_kernel<<<gemm640, 256>>>(gg, ff2w, ff2b, t, t, Mrows, Cdim, FFH);

    // proj_out + input residual
    sgemm_kernel<<<gemm640, 256>>>(t, prw, prb, x, out, Mrows, Cdim, Cdim);
}

// round 4
// speedup vs baseline: 1.9382x; 1.9382x over previous
#include <cuda_runtime.h>
#include <math.h>
#include <stdint.h>

// ---------------- problem dims ----------------
#define Bn    8
#define Sq    1024
#define Cdim  640
#define Tctx  77
#define CTXD  768
#define NHEAD 8
#define HSZ   80
#define FFD   5120
#define FFH   2560
#define Mrows (Bn * Sq)      // 8192
#define MCTX  (Bn * Tctx)    // 616

// ---------------- scratch (static device, no allocs allowed) ----------------
__device__ float g_ln  [(size_t)Mrows * Cdim];
__device__ float g_y   [(size_t)Mrows * Cdim];
__device__ float g_q   [(size_t)Mrows * Cdim];
__device__ float g_k   [(size_t)Mrows * Cdim];
__device__ float g_v   [(size_t)Mrows * Cdim];
__device__ float g_at  [(size_t)Mrows * Cdim];
__device__ float g_t   [(size_t)Mrows * Cdim];
__device__ float g_sc  [(size_t)64 * 1024 * 1024];   // scores: 64 bh x 1024 x 1024
__device__ float g_ff  [(size_t)Mrows * FFD];
__device__ float g_gg  [(size_t)Mrows * FFH];

// ---------------- GroupNorm ----------------
__global__ void groupnorm_kernel(const float* __restrict__ x,
                                 const float* __restrict__ gamma,
                                 const float* __restrict__ beta,
                                 float* __restrict__ out)
{
    const int b = blockIdx.x >> 5;
    const int g = blockIdx.x & 31;
    const float* base = x + (size_t)b * Sq * Cdim + g * 20;
    float sum = 0.f, sq = 0.f;
    for (int idx = threadIdx.x; idx < Sq * 20; idx += 256) {
        int hw = idx / 20, c = idx % 20;
        float v = base[(size_t)hw * Cdim + c];
        sum += v; sq += v * v;
    }
    #pragma unroll
    for (int o = 16; o > 0; o >>= 1) {
        sum += __shfl_xor_sync(0xffffffffu, sum, o);
        sq  += __shfl_xor_sync(0xffffffffu, sq,  o);
    }
    __shared__ float s1[8], s2[8];
    const int wid = threadIdx.x >> 5, lane = threadIdx.x & 31;
    if (lane == 0) { s1[wid] = sum; s2[wid] = sq; }
    __syncthreads();
    float tot = 0.f, totq = 0.f;
    #pragma unroll
    for (int i = 0; i < 8; i++) { tot += s1[i]; totq += s2[i]; }
    const float mean = tot * (1.f / 20480.f);
    const float var  = totq * (1.f / 20480.f) - mean * mean;
    const float rstd = rsqrtf(var + 1e-5f);
    float* ob = out + (size_t)b * Sq * Cdim + g * 20;
    for (int idx = threadIdx.x; idx < Sq * 20; idx += 256) {
        int hw = idx / 20, c = idx % 20;
        float v = base[(size_t)hw * Cdim + c];
        ob[(size_t)hw * Cdim + c] = (v - mean) * rstd * gamma[g * 20 + c] + beta[g * 20 + c];
    }
}

// ---------------- LayerNorm (640) ----------------
__global__ void layernorm_kernel(const float* __restrict__ x,
                                 const float* __restrict__ g,
                                 const float* __restrict__ b,
                                 float* __restrict__ out, int rows)
{
    const int w = (blockIdx.x << 3) + (threadIdx.x >> 5);
    if (w >= rows) return;
    const int lane = threadIdx.x & 31;
    const float* row = x + (size_t)w * Cdim;
    float4 v[5];
    float sum = 0.f, sq = 0.f;
    #pragma unroll
    for (int p = 0; p < 5; p++) {
        v[p] = *reinterpret_cast<const float4*>(row + (lane + 32 * p) * 4);
        sum += v[p].x + v[p].y + v[p].z + v[p].w;
        sq  += v[p].x * v[p].x + v[p].y * v[p].y + v[p].z * v[p].z + v[p].w * v[p].w;
    }
    #pragma unroll
    for (int o = 16; o > 0; o >>= 1) {
        sum += __shfl_xor_sync(0xffffffffu, sum, o);
        sq  += __shfl_xor_sync(0xffffffffu, sq,  o);
    }
    const float mean = sum * (1.f / 640.f);
    const float var  = sq * (1.f / 640.f) - mean * mean;
    const float rstd = rsqrtf(var + 1e-5f);
    float* orow = out + (size_t)w * Cdim;
    #pragma unroll
    for (int p = 0; p < 5; p++) {
        const int off = (lane + 32 * p) * 4;
        const float4 g4 = *reinterpret_cast<const float4*>(g + off);
        const float4 b4 = *reinterpret_cast<const float4*>(b + off);
        float4 o;
        o.x = (v[p].x - mean) * rstd * g4.x + b4.x;
        o.y = (v[p].y - mean) * rstd * g4.y + b4.y;
        o.z = (v[p].z - mean) * rstd * g4.z + b4.z;
        o.w = (v[p].w - mean) * rstd * g4.w + b4.w;
        *reinterpret_cast<float4*>(orow + off) = o;
    }
}

// ---------------- TF32 tensor-core GEMM ----------------
// C[M,N] = A[M,K] @ B[K,N] (+bias)(+residual)
// 128x128x32 block tile, 256 threads (8 warps), warp tile 64x32 (warps 2x4).
// smem: As[k][m] pitch 132, Bs[k][n] pitch 132 (fragment LDS conflict-free).
__device__ __forceinline__ uint32_t f2tf32(float f)
{
    uint32_t u;
    asm("cvt.rna.tf32.f32 %0, %1;" : "=r"(u) : "f"(f));
    return u;
}

__device__ __forceinline__ void mma_tf32(float* c, const uint32_t* a, const uint32_t* b)
{
    asm volatile(
        "mma.sync.aligned.m16n8k8.row.col.f32.tf32.tf32.f32 "
        "{%0,%1,%2,%3}, {%4,%5,%6,%7}, {%8,%9}, {%0,%1,%2,%3};"
        : "+f"(c[0]), "+f"(c[1]), "+f"(c[2]), "+f"(c[3])
        : "r"(a[0]), "r"(a[1]), "r"(a[2]), "r"(a[3]), "r"(b[0]), "r"(b[1]));
}

#define SP 132   // smem pitch (floats)

__global__ __launch_bounds__(256, 2)
void tf32_gemm_kernel(const float* __restrict__ A, const float* __restrict__ B,
                      const float* __restrict__ bias, const float* __restrict__ Res,
                      float* __restrict__ C, int M, int N, int K)
{
    __shared__ uint32_t As[32 * SP];
    __shared__ uint32_t Bs[32 * SP];
    const int tid  = threadIdx.x;
    const int lane = tid & 31, warp = tid >> 5;
    const int g = lane >> 2, tig = lane & 3;
    const int wm = (warp >> 2) * 64;       // 0 / 64
    const int wn = (warp & 3) * 32;        // 0..96
    const int row0 = blockIdx.y * 128, col0 = blockIdx.x * 128;

    // staging maps
    const int am = tid >> 3;               // 0..31  (plus l*32)
    const int ak = (tid & 7) * 4;          // 0..28
    const int bk = tid >> 5;               // 0..7   (plus l*8)
    const int bn = (tid & 31) * 4;         // 0..124

    float acc[4][4][4];
    #pragma unroll
    for (int mt = 0; mt < 4; mt++)
        #pragma unroll
        for (int nt = 0; nt < 4; nt++)
            #pragma unroll
            for (int i = 0; i < 4; i++) acc[mt][nt][i] = 0.f;

    const int KT = K >> 5;
    for (int kt = 0; kt < KT; kt++) {
        // --- stage A (transposed -> As[k][m]) ---
        #pragma unroll
        for (int l = 0; l < 4; l++) {
            const int m = am + l * 32;
            const int ar = row0 + m;
            float4 av = make_float4(0.f, 0.f, 0.f, 0.f);
            if (ar < M)
                av = *reinterpret_cast<const float4*>(A + (size_t)ar * K + kt * 32 + ak);
            As[(ak + 0) * SP + m] = f2tf32(av.x);
            As[(ak + 1) * SP + m] = f2tf32(av.y);
            As[(ak + 2) * SP + m] = f2tf32(av.z);
            As[(ak + 3) * SP + m] = f2tf32(av.w);
        }
        // --- stage B -> Bs[k][n] ---
        #pragma unroll
        for (int l = 0; l < 4; l++) {
            const int kk = bk + l * 8;
            const float4 bv = *reinterpret_cast<const float4*>(
                B + (size_t)(kt * 32 + kk) * N + col0 + bn);
            uint4 u;
            u.x = f2tf32(bv.x); u.y = f2tf32(bv.y);
            u.z = f2tf32(bv.z); u.w = f2tf32(bv.w);
            *reinterpret_cast<uint4*>(&Bs[kk * SP + bn]) = u;
        }
        __syncthreads();

        #pragma unroll
        for (int ks = 0; ks < 4; ks++) {
            const int k0 = ks * 8;
            uint32_t af[4][4];
            #pragma unroll
            for (int mt = 0; mt < 4; mt++) {
                const int m = wm + mt * 16 + g;
                af[mt][0] = As[(k0 + tig) * SP + m];
                af[mt][1] = As[(k0 + tig) * SP + m + 8];
                af[mt][2] = As[(k0 + tig + 4) * SP + m];
                af[mt][3] = As[(k0 + tig + 4) * SP + m + 8];
            }
            uint32_t bf[4][2];
            #pragma unroll
            for (int nt = 0; nt < 4; nt++) {
                const int n = wn + nt * 8 + g;
                bf[nt][0] = Bs[(k0 + tig) * SP + n];
                bf[nt][1] = Bs[(k0 + tig + 4) * SP + n];
            }
            #pragma unroll
            for (int mt = 0; mt < 4; mt++)
                #pragma unroll
                for (int nt = 0; nt < 4; nt++)
                    mma_tf32(acc[mt][nt], af[mt], bf[nt]);
        }
        __syncthreads();
    }

    // --- epilogue ---
    #pragma unroll
    for (int mt = 0; mt < 4; mt++) {
        const int r0 = row0 + wm + mt * 16 + g;
        const int r1 = r0 + 8;
        #pragma unroll
        for (int nt = 0; nt < 4; nt++) {
            const int c = col0 + wn + nt * 8 + 2 * tig;
            float2 v0 = make_float2(acc[mt][nt][0], acc[mt][nt][1]);
            float2 v1 = make_float2(acc[mt][nt][2], acc[mt][nt][3]);
            if (bias) {
                const float2 bb = *reinterpret_cast<const float2*>(bias + c);
                v0.x += bb.x; v0.y += bb.y;
                v1.x += bb.x; v1.y += bb.y;
            }
            if (r0 < M) {
                if (Res) {
                    const float2 rv = *reinterpret_cast<const float2*>(Res + (size_t)r0 * N + c);
                    v0.x += rv.x; v0.y += rv.y;
                }
                *reinterpret_cast<float2*>(C + (size_t)r0 * N + c) = v0;
            }
            if (r1 < M) {
                if (Res) {
                    const float2 rv = *reinterpret_cast<const float2*>(Res + (size_t)r1 * N + c);
                    v1.x += rv.x; v1.y += rv.y;
                }
                *reinterpret_cast<float2*>(C + (size_t)r1 * N + c) = v1;
            }
        }
    }
}

// ---------------- attention scores ----------------
__global__ __launch_bounds__(256)
void attn_scores_kernel(const float* __restrict__ Q, const float* __restrict__ Kb,
                        float* __restrict__ Sout, int Tk, int kSeq)
{
    const int bh = blockIdx.z, b = bh >> 3, n = bh & 7;
    const float* qb = Q + (size_t)b * Sq * Cdim + n * HSZ;
    const float* kb = Kb + (size_t)b * kSeq * Cdim + n * HSZ;
    float* sb = Sout + (size_t)bh * Sq * Tk;
    const int i0 = blockIdx.y * 64, j0 = blockIdx.x * 64;
    __shared__ float Qs[16][64], Ks[16][64];
    const int tid = threadIdx.x, tx = tid & 15, ty = tid >> 4;
    const int lr = tid >> 2, lc = (tid & 3) * 4;
    float acc[4][4] = {};
    for (int kk = 0; kk < HSZ; kk += 16) {
        const float4 qv = *reinterpret_cast<const float4*>(qb + (size_t)(i0 + lr) * Cdim + kk + lc);
        Qs[lc + 0][lr] = qv.x; Qs[lc + 1][lr] = qv.y; Qs[lc + 2][lr] = qv.z; Qs[lc + 3][lr] = qv.w;
        float4 kv = make_float4(0.f, 0.f, 0.f, 0.f);
        if (j0 + lr < Tk) kv = *reinterpret_cast<const float4*>(kb + (size_t)(j0 + lr) * Cdim + kk + lc);
        Ks[lc + 0][lr] = kv.x; Ks[lc + 1][lr] = kv.y; Ks[lc + 2][lr] = kv.z; Ks[lc + 3][lr] = kv.w;
        __syncthreads();
        #pragma unroll
        for (int k = 0; k < 16; k++) {
            const float4 a = *reinterpret_cast<const float4*>(&Qs[k][ty * 4]);
            const float4 bb = *reinterpret_cast<const float4*>(&Ks[k][tx * 4]);
            const float af[4] = {a.x, a.y, a.z, a.w};
            const float bf[4] = {bb.x, bb.y, bb.z, bb.w};
            #pragma unroll
            for (int i = 0; i < 4; i++)
                #pragma unroll
                for (int j = 0; j < 4; j++) acc[i][j] += af[i] * bf[j];
        }
        __syncthreads();
    }
    const float scale = 0.11180339887498949f;
    #pragma unroll
    for (int i = 0; i < 4; i++) {
        const int r = i0 + ty * 4 + i;
        #pragma unroll
        for (int j = 0; j < 4; j++) {
            const int c = j0 + tx * 4 + j;
            if (c < Tk) sb[(size_t)r * Tk + c] = acc[i][j] * scale;
        }
    }
}

// ---------------- softmax ----------------
__global__ void softmax_kernel(float* __restrict__ S, int rows, int L)
{
    const int w = (blockIdx.x << 3) + (threadIdx.x >> 5);
    if (w >= rows) return;
    const int lane = threadIdx.x & 31;
    float* row = S + (size_t)w * L;
    float v[32];
    float m = -3.4e38f;
    #pragma unroll
    for (int p = 0; p < 32; p++) {
        const int i = lane + (p << 5);
        v[p] = (i < L) ? row[i] : -3.4e38f;
        m = fmaxf(m, v[p]);
    }
    #pragma unroll
    for (int o = 16; o > 0; o >>= 1) m = fmaxf(m, __shfl_xor_sync(0xffffffffu, m, o));
    float s = 0.f;
    #pragma unroll
    for (int p = 0; p < 32; p++) {
        const int i = lane + (p << 5);
        if (i < L) { v[p] = __expf(v[p] - m); s += v[p]; }
    }
    #pragma unroll
    for (int o = 16; o > 0; o >>= 1) s += __shfl_xor_sync(0xffffffffu, s, o);
    const float inv = 1.f / s;
    #pragma unroll
    for (int p = 0; p < 32; p++) {
        const int i = lane + (p << 5);
        if (i < L) row[i] = v[p] * inv;
    }
}

// ---------------- attn PV ----------------
__global__ __launch_bounds__(256)
void attn_pv_kernel(const float* __restrict__ P, const float* __restrict__ V,
                    float* __restrict__ O, int Tk, int vSeq)
{
    const int bh = blockIdx.z, b = bh >> 3, n = bh & 7;
    const float* pb = P + (size_t)bh * Sq * Tk;
    const float* vb = V + (size_t)b * vSeq * Cdim + n * HSZ;
    float* ob = O + (size_t)b * Sq * Cdim + n * HSZ;
    const int i0 = blockIdx.x * 64;
    __shared__ float Ps[16][64];
    __shared__ float Vs[16][80];
    const int tid = threadIdx.x, tx = tid & 15, ty = tid >> 4;
    const int lr = tid >> 2, lc = (tid & 3) * 4;
    float acc[4][5] = {};
    for (int t0 = 0; t0 < Tk; t0 += 16) {
        #pragma unroll
        for (int l = 0; l < 4; l++) {
            const int t = t0 + lc + l;
            Ps[lc + l][lr] = (t < Tk) ? pb[(size_t)(i0 + lr) * Tk + t] : 0.f;
        }
        for (int e = tid; e < 16 * 80; e += 256) {
            const int tr = e / 80, c = e % 80;
            Vs[tr][c] = (t0 + tr < Tk) ? vb[(size_t)(t0 + tr) * Cdim + c] : 0.f;
        }
        __syncthreads();
        #pragma unroll
        for (int k = 0; k < 16; k++) {
            const float p0 = Ps[k][ty * 4 + 0], p1 = Ps[k][ty * 4 + 1];
            const float p2 = Ps[k][ty * 4 + 2], p3 = Ps[k][ty * 4 + 3];
            #pragma unroll
            for (int j = 0; j < 5; j++) {
                const float vv = Vs[k][tx + 16 * j];
                acc[0][j] += p0 * vv; acc[1][j] += p1 * vv;
                acc[2][j] += p2 * vv; acc[3][j] += p3 * vv;
            }
        }
        __syncthreads();
    }
    #pragma unroll
    for (int i = 0; i < 4; i++) {
        const int r = i0 + ty * 4 + i;
        #pragma unroll
        for (int j = 0; j < 5; j++)
            ob[(size_t)r * Cdim + tx + 16 * j] = acc[i][j];
    }
}

// ---------------- GEGLU ----------------
__device__ __forceinline__ float geglu_one(float xh, float g)
{
    const float t = tanhf(g * 0.7978845608f * (1.f + 0.044715f * g * g));
    return xh * 0.5f * g * (1.f + t);
}

__global__ void geglu_kernel(const float* __restrict__ ff, float* __restrict__ out)
{
    const size_t idx = (size_t)blockIdx.x * blockDim.x + threadIdx.x;
    if (idx >= (size_t)Mrows * (FFH / 4)) return;
    const size_t row = idx / (FFH / 4);
    const int c4 = (int)(idx % (FFH / 4));
    const float4 xh = *reinterpret_cast<const float4*>(ff + row * FFD + c4 * 4);
    const float4 gt = *reinterpret_cast<const float4*>(ff + row * FFD + FFH + c4 * 4);
    float4 o;
    o.x = geglu_one(xh.x, gt.x);
    o.y = geglu_one(xh.y, gt.y);
    o.z = geglu_one(xh.z, gt.z);
    o.w = geglu_one(xh.w, gt.w);
    *reinterpret_cast<float4*>(out + row * FFH + c4 * 4) = o;
}

// ---------------- host orchestration ----------------
extern "C" void kernel_launch(void* const* d_in, const int* in_sizes, int n_in,
                              void* d_out, int out_size)
{
    (void)in_sizes; (void)n_in; (void)out_size;
    const float* x     = (const float*)d_in[0];
    const float* ctx   = (const float*)d_in[1];
    const float* gn_g  = (const float*)d_in[2];
    const float* gn_b  = (const float*)d_in[3];
    const float* piw   = (const float*)d_in[4];
    const float* pib   = (const float*)d_in[5];
    const float* ln1g  = (const float*)d_in[6];
    const float* ln1b  = (const float*)d_in[7];
    const float* a1q   = (const float*)d_in[8];
    const float* a1k   = (const float*)d_in[9];
    const float* a1v   = (const float*)d_in[10];
    const float* a1o   = (const float*)d_in[11];
    const float* a1ob  = (const float*)d_in[12];
    const float* ln2g  = (const float*)d_in[13];
    const float* ln2b  = (const float*)d_in[14];
    const float* a2q   = (const float*)d_in[15];
    const float* a2k   = (const float*)d_in[16];
    const float* a2v   = (const float*)d_in[17];
    const float* a2o   = (const float*)d_in[18];
    const float* a2ob  = (const float*)d_in[19];
    const float* ln3g  = (const float*)d_in[20];
    const float* ln3b  = (const float*)d_in[21];
    const float* ff1w  = (const float*)d_in[22];
    const float* ff1b  = (const float*)d_in[23];
    const float* ff2w  = (const float*)d_in[24];
    const float* ff2b  = (const float*)d_in[25];
    const float* prw   = (const float*)d_in[26];
    const float* prb   = (const float*)d_in[27];
    float* out = (float*)d_out;

    float *ln, *y, *q, *k, *v, *at, *t, *sc, *ff, *gg;
    cudaGetSymbolAddress((void**)&ln, g_ln);
    cudaGetSymbolAddress((void**)&y,  g_y);
    cudaGetSymbolAddress((void**)&q,  g_q);
    cudaGetSymbolAddress((void**)&k,  g_k);
    cudaGetSymbolAddress((void**)&v,  g_v);
    cudaGetSymbolAddress((void**)&at, g_at);
    cudaGetSymbolAddress((void**)&t,  g_t);
    cudaGetSymbolAddress((void**)&sc, g_sc);
    cudaGetSymbolAddress((void**)&ff, g_ff);
    cudaGetSymbolAddress((void**)&gg, g_gg);

    const dim3 gemm640(Cdim / 128, Mrows / 128);        // (5, 64)
    const dim3 gemmCtx(Cdim / 128, (MCTX + 127) / 128); // (5, 5)
    const dim3 gemmFF(FFD / 128, Mrows / 128);          // (40, 64)

    // y = proj_in(group_norm(x))
    groupnorm_kernel<<<Bn * 32, 256>>>(x, gn_g, gn_b, ln);
    tf32_gemm_kernel<<<gemm640, 256>>>(ln, piw, pib, nullptr, y, Mrows, Cdim, Cdim);

    // self attention
    layernorm_kernel<<<Mrows / 8, 256>>>(y, ln1g, ln1b, ln, Mrows);
    tf32_gemm_kernel<<<gemm640, 256>>>(ln, a1q, nullptr, nullptr, q, Mrows, Cdim, Cdim);
    tf32_gemm_kernel<<<gemm640, 256>>>(ln, a1k, nullptr, nullptr, k, Mrows, Cdim, Cdim);
    tf32_gemm_kernel<<<gemm640, 256>>>(ln, a1v, nullptr, nullptr, v, Mrows, Cdim, Cdim);
    attn_scores_kernel<<<dim3(16, 16, 64), 256>>>(q, k, sc, Sq, Sq);
    softmax_kernel<<<(64 * Sq) / 8, 256>>>(sc, 64 * Sq, Sq);
    attn_pv_kernel<<<dim3(16, 1, 64), 256>>>(sc, v, at, Sq, Sq);
    tf32_gemm_kernel<<<gemm640, 256>>>(at, a1o, a1ob, y, t, Mrows, Cdim, Cdim);

    // cross attention
    layernorm_kernel<<<Mrows / 8, 256>>>(t, ln2g, ln2b, ln, Mrows);
    tf32_gemm_kernel<<<gemmCtx, 256>>>(ctx, a2k, nullptr, nullptr, k, MCTX, Cdim, CTXD);
    tf32_gemm_kernel<<<gemmCtx, 256>>>(ctx, a2v, nullptr, nullptr, v, MCTX, Cdim, CTXD);
    tf32_gemm_kernel<<<gemm640, 256>>>(ln, a2q, nullptr, nullptr, q, Mrows, Cdim, Cdim);
    attn_scores_kernel<<<dim3(2, 16, 64), 256>>>(q, k, sc, Tctx, Tctx);
    softmax_kernel<<<(64 * Sq) / 8, 256>>>(sc, 64 * Sq, Tctx);
    attn_pv_kernel<<<dim3(16, 1, 64), 256>>>(sc, v, at, Tctx, Tctx);
    tf32_gemm_kernel<<<gemm640, 256>>>(at, a2o, a2ob, t, t, Mrows, Cdim, Cdim);

    // GEGLU feed-forward
    layernorm_kernel<<<Mrows / 8, 256>>>(t, ln3g, ln3b, ln, Mrows);
    tf32_gemm_kernel<<<gemmFF, 256>>>(ln, ff1w, ff1b, nullptr, ff, Mrows, FFD, Cdim);
    geglu_kernel<<<(Mrows * (FFH / 4)) / 256, 256>>>(ff, gg);
    tf32_gemm_kernel<<<gemm640, 256>>>(gg, ff2w, ff2b, t, t, Mrows, Cdim, FFH);

    // proj_out + input residual
    tf32_gemm_kernel<<<gemm640, 256>>>(t, prw, prb, x, out, Mrows, Cdim, Cdim);
}

// round 6
// speedup vs baseline: 2.5951x; 1.3389x over previous
#include <cuda_runtime.h>
#include <math.h>
#include <stdint.h>

// ---------------- problem dims ----------------
#define Bn    8
#define Sq    1024
#define Cdim  640
#define Tctx  77
#define TPAD  96
#define CTXD  768
#define NHEAD 8
#define HSZ   80
#define FFD   5120
#define FFH   2560
#define Mrows (Bn * Sq)      // 8192
#define MCTX  (Bn * Tctx)    // 616

// ---------------- scratch ----------------
__device__ float g_ln  [(size_t)Mrows * Cdim];
__device__ float g_y   [(size_t)Mrows * Cdim];
__device__ float g_q   [(size_t)Mrows * Cdim];
__device__ float g_k   [(size_t)Mrows * Cdim];
__device__ float g_v   [(size_t)Mrows * Cdim];
__device__ float g_at  [(size_t)Mrows * Cdim];
__device__ float g_t   [(size_t)Mrows * Cdim];
__device__ float g_sc  [(size_t)64 * 1024 * 1024];
__device__ float g_ff  [(size_t)Mrows * FFD];
__device__ float g_gg  [(size_t)Mrows * FFH];

// ---------------- helpers ----------------
__device__ __forceinline__ void mma_tf32(float* c, const uint32_t* a, const uint32_t* b)
{
    asm volatile(
        "mma.sync.aligned.m16n8k8.row.col.f32.tf32.tf32.f32 "
        "{%0,%1,%2,%3}, {%4,%5,%6,%7}, {%8,%9}, {%0,%1,%2,%3};"
        : "+f"(c[0]), "+f"(c[1]), "+f"(c[2]), "+f"(c[3])
        : "r"(a[0]), "r"(a[1]), "r"(a[2]), "r"(a[3]), "r"(b[0]), "r"(b[1]));
}

__device__ __forceinline__ void cp16(uint32_t dst, const void* src, bool pred)
{
    const int sz = pred ? 16 : 0;
    asm volatile("cp.async.cg.shared.global [%0], [%1], 16, %2;\n"
                 :: "r"(dst), "l"(src), "r"(sz));
}
__device__ __forceinline__ void cp_commit() { asm volatile("cp.async.commit_group;\n"); }
template <int N>
__device__ __forceinline__ void cp_wait() { asm volatile("cp.async.wait_group %0;\n" :: "n"(N)); }

__device__ __forceinline__ uint32_t fu(float f) { return __float_as_uint(f); }

// ---------------- GroupNorm ----------------
__global__ void groupnorm_kernel(const float* __restrict__ x,
                                 const float* __restrict__ gamma,
                                 const float* __restrict__ beta,
                                 float* __restrict__ out)
{
    const int b = blockIdx.x >> 5;
    const int g = blockIdx.x & 31;
    const float* base = x + (size_t)b * Sq * Cdim + g * 20;
    float sum = 0.f, sq = 0.f;
    for (int idx = threadIdx.x; idx < Sq * 20; idx += 256) {
        int hw = idx / 20, c = idx % 20;
        float v = base[(size_t)hw * Cdim + c];
        sum += v; sq += v * v;
    }
    #pragma unroll
    for (int o = 16; o > 0; o >>= 1) {
        sum += __shfl_xor_sync(0xffffffffu, sum, o);
        sq  += __shfl_xor_sync(0xffffffffu, sq,  o);
    }
    __shared__ float s1[8], s2[8];
    const int wid = threadIdx.x >> 5, lane = threadIdx.x & 31;
    if (lane == 0) { s1[wid] = sum; s2[wid] = sq; }
    __syncthreads();
    float tot = 0.f, totq = 0.f;
    #pragma unroll
    for (int i = 0; i < 8; i++) { tot += s1[i]; totq += s2[i]; }
    const float mean = tot * (1.f / 20480.f);
    const float var  = totq * (1.f / 20480.f) - mean * mean;
    const float rstd = rsqrtf(var + 1e-5f);
    float* ob = out + (size_t)b * Sq * Cdim + g * 20;
    for (int idx = threadIdx.x; idx < Sq * 20; idx += 256) {
        int hw = idx / 20, c = idx % 20;
        float v = base[(size_t)hw * Cdim + c];
        ob[(size_t)hw * Cdim + c] = (v - mean) * rstd * gamma[g * 20 + c] + beta[g * 20 + c];
    }
}

// ---------------- LayerNorm ----------------
__global__ void layernorm_kernel(const float* __restrict__ x,
                                 const float* __restrict__ g,
                                 const float* __restrict__ b,
                                 float* __restrict__ out, int rows)
{
    const int w = (blockIdx.x << 3) + (threadIdx.x >> 5);
    if (w >= rows) return;
    const int lane = threadIdx.x & 31;
    const float* row = x + (size_t)w * Cdim;
    float4 v[5];
    float sum = 0.f, sq = 0.f;
    #pragma unroll
    for (int p = 0; p < 5; p++) {
        v[p] = *reinterpret_cast<const float4*>(row + (lane + 32 * p) * 4);
        sum += v[p].x + v[p].y + v[p].z + v[p].w;
        sq  += v[p].x * v[p].x + v[p].y * v[p].y + v[p].z * v[p].z + v[p].w * v[p].w;
    }
    #pragma unroll
    for (int o = 16; o > 0; o >>= 1) {
        sum += __shfl_xor_sync(0xffffffffu, sum, o);
        sq  += __shfl_xor_sync(0xffffffffu, sq,  o);
    }
    const float mean = sum * (1.f / 640.f);
    const float var  = sq * (1.f / 640.f) - mean * mean;
    const float rstd = rsqrtf(var + 1e-5f);
    float* orow = out + (size_t)w * Cdim;
    #pragma unroll
    for (int p = 0; p < 5; p++) {
        const int off = (lane + 32 * p) * 4;
        const float4 g4 = *reinterpret_cast<const float4*>(g + off);
        const float4 b4 = *reinterpret_cast<const float4*>(b + off);
        float4 o;
        o.x = (v[p].x - mean) * rstd * g4.x + b4.x;
        o.y = (v[p].y - mean) * rstd * g4.y + b4.y;
        o.z = (v[p].z - mean) * rstd * g4.z + b4.z;
        o.w = (v[p].w - mean) * rstd * g4.w + b4.w;
        *reinterpret_cast<float4*>(orow + off) = o;
    }
}

// ---------------- pipelined TF32 GEMM ----------------
// 128x128x32 tile, 8 warps (2x4), warp tile 64x32, cp.async 2-stage.
#define ASP 36     // As pitch: bank = 4g+tig -> conflict-free
#define BSP 136    // Bs pitch: bank = 8tig+g -> conflict-free
#define ASTG (128 * ASP)
#define BSTG (32 * BSP)
#define GEMM_SMEM ((2 * ASTG + 2 * BSTG) * 4)

__global__ __launch_bounds__(256, 2)
void tf32_gemm_kernel(const float* __restrict__ A, const float* __restrict__ B,
                      const float* __restrict__ bias, const float* __restrict__ Res,
                      float* __restrict__ C, int M, int N, int K)
{
    extern __shared__ float smem[];
    float* As = smem;                    // [2][128*ASP]
    float* Bs = smem + 2 * ASTG;         // [2][32*BSP]
    const int tid  = threadIdx.x;
    const int lane = tid & 31, warp = tid >> 5;
    const int g = lane >> 2, tig = lane & 3;
    const int wm = (warp >> 2) * 64;
    const int wn = (warp & 3) * 32;
    const int row0 = blockIdx.y * 128, col0 = blockIdx.x * 128;

    // staging maps
    const int am = tid >> 1, ak = (tid & 1) * 16;   // A: row am, 16 floats from ak
    const int bk = tid >> 3, bn = (tid & 7) * 16;   // B: row bk, 16 floats from bn
    const bool arow_ok = (row0 + am) < M;
    const float* agp = A + (size_t)(row0 + am) * K + ak;
    const float* bgp = B + (size_t)bk * N + col0 + bn;
    const uint32_t as_d = (uint32_t)__cvta_generic_to_shared(As + am * ASP + ak);
    const uint32_t bs_d = (uint32_t)__cvta_generic_to_shared(Bs + bk * BSP + bn);

    float acc[4][4][4];
    #pragma unroll
    for (int mt = 0; mt < 4; mt++)
        #pragma unroll
        for (int nt = 0; nt < 4; nt++)
            #pragma unroll
            for (int i = 0; i < 4; i++) acc[mt][nt][i] = 0.f;

    const int KT = K >> 5;

    // prologue: stage tile 0
    {
        #pragma unroll
        for (int l = 0; l < 4; l++) cp16(as_d + l * 16, agp + l * 4, arow_ok);
        #pragma unroll
        for (int l = 0; l < 4; l++) cp16(bs_d + l * 16, bgp + l * 4, true);
        cp_commit();
    }

    for (int kt = 0; kt < KT; kt++) {
        const int s = kt & 1;
        if (kt + 1 < KT) {
            const int s2 = s ^ 1;
            const float* ag = agp + (kt + 1) * 32;
            const float* bg = bgp + (size_t)(kt + 1) * 32 * N;
            #pragma unroll
            for (int l = 0; l < 4; l++) cp16(as_d + s2 * (ASTG * 4) + l * 16, ag + l * 4, arow_ok);
            #pragma unroll
            for (int l = 0; l < 4; l++) cp16(bs_d + s2 * (BSTG * 4) + l * 16, bg + l * 4, true);
            cp_commit();
            cp_wait<1>();
        } else {
            cp_wait<0>();
        }
        __syncthreads();

        const float* as = As + s * ASTG;
        const float* bs = Bs + s * BSTG;
        #pragma unroll
        for (int ks = 0; ks < 4; ks++) {
            const int kq = ks * 8 + tig;
            uint32_t af[4][4];
            #pragma unroll
            for (int mt = 0; mt < 4; mt++) {
                const int m = wm + mt * 16 + g;
                af[mt][0] = fu(as[m * ASP + kq]);
                af[mt][1] = fu(as[(m + 8) * ASP + kq]);
                af[mt][2] = fu(as[m * ASP + kq + 4]);
                af[mt][3] = fu(as[(m + 8) * ASP + kq + 4]);
            }
            uint32_t bf[4][2];
            #pragma unroll
            for (int nt = 0; nt < 4; nt++) {
                const int n = wn + nt * 8 + g;
                bf[nt][0] = fu(bs[kq * BSP + n]);
                bf[nt][1] = fu(bs[(kq + 4) * BSP + n]);
            }
            #pragma unroll
            for (int mt = 0; mt < 4; mt++)
                #pragma unroll
                for (int nt = 0; nt < 4; nt++)
                    mma_tf32(acc[mt][nt], af[mt], bf[nt]);
        }
        __syncthreads();
    }

    // epilogue
    #pragma unroll
    for (int mt = 0; mt < 4; mt++) {
        const int r0 = row0 + wm + mt * 16 + g;
        const int r1 = r0 + 8;
        #pragma unroll
        for (int nt = 0; nt < 4; nt++) {
            const int c = col0 + wn + nt * 8 + 2 * tig;
            float2 v0 = make_float2(acc[mt][nt][0], acc[mt][nt][1]);
            float2 v1 = make_float2(acc[mt][nt][2], acc[mt][nt][3]);
            if (bias) {
                const float2 bb = *reinterpret_cast<const float2*>(bias + c);
                v0.x += bb.x; v0.y += bb.y;
                v1.x += bb.x; v1.y += bb.y;
            }
            if (r0 < M) {
                if (Res) {
                    const float2 rv = *reinterpret_cast<const float2*>(Res + (size_t)r0 * N + c);
                    v0.x += rv.x; v0.y += rv.y;
                }
                *reinterpret_cast<float2*>(C + (size_t)r0 * N + c) = v0;
            }
            if (r1 < M) {
                if (Res) {
                    const float2 rv = *reinterpret_cast<const float2*>(Res + (size_t)r1 * N + c);
                    v1.x += rv.x; v1.y += rv.y;
                }
                *reinterpret_cast<float2*>(C + (size_t)r1 * N + c) = v1;
            }
        }
    }
}

// ---------------- MMA attention scores ----------------
// 64x64 tile per block, 4 warps (2x2), warp tile 32x32, K=80 staged once.
#define QP 84   // bank mult on g = 20 -> conflict-free
__global__ __launch_bounds__(128)
void attn_scores_mma(const float* __restrict__ Q, const float* __restrict__ Kb,
                     float* __restrict__ S, int Tk, int Tpad, int kSeq)
{
    __shared__ float Qs[64 * QP];
    __shared__ float Ks[64 * QP];
    const int bh = blockIdx.z, b = bh >> 3, n = bh & 7;
    const float* qb = Q + (size_t)b * Sq * Cdim + n * HSZ;
    const float* kb = Kb + (size_t)b * kSeq * Cdim + n * HSZ;
    float* sb = S + (size_t)bh * Sq * Tpad;
    const int i0 = blockIdx.y * 64, j0 = blockIdx.x * 64;
    const int tid = threadIdx.x;

    for (int e = tid; e < 64 * 20; e += 128) {
        const int r = e / 20, c = (e % 20) * 4;
        const float4 qv = *reinterpret_cast<const float4*>(qb + (size_t)(i0 + r) * Cdim + c);
        *reinterpret_cast<float4*>(&Qs[r * QP + c]) = qv;
        float4 kv = make_float4(0.f, 0.f, 0.f, 0.f);
        if (j0 + r < Tk)
            kv = *reinterpret_cast<const float4*>(kb + (size_t)(j0 + r) * Cdim + c);
        *reinterpret_cast<float4*>(&Ks[r * QP + c]) = kv;
    }
    __syncthreads();

    const int lane = tid & 31, warp = tid >> 5;
    const int g = lane >> 2, tig = lane & 3;
    const int wm = (warp >> 1) * 32, wn = (warp & 1) * 32;

    float acc[2][4][4];
    #pragma unroll
    for (int mt = 0; mt < 2; mt++)
        #pragma unroll
        for (int nt = 0; nt < 4; nt++)
            #pragma unroll
            for (int i = 0; i < 4; i++) acc[mt][nt][i] = 0.f;

    #pragma unroll
    for (int ks = 0; ks < 10; ks++) {
        const int kq = ks * 8 + tig;
        uint32_t af[2][4];
        #pragma unroll
        for (int mt = 0; mt < 2; mt++) {
            const int m = wm + mt * 16 + g;
            af[mt][0] = fu(Qs[m * QP + kq]);
            af[mt][1] = fu(Qs[(m + 8) * QP + kq]);
            af[mt][2] = fu(Qs[m * QP + kq + 4]);
            af[mt][3] = fu(Qs[(m + 8) * QP + kq + 4]);
        }
        uint32_t bf[4][2];
        #pragma unroll
        for (int nt = 0; nt < 4; nt++) {
            const int nn = wn + nt * 8 + g;
            bf[nt][0] = fu(Ks[nn * QP + kq]);
            bf[nt][1] = fu(Ks[nn * QP + kq + 4]);
        }
        #pragma unroll
        for (int mt = 0; mt < 2; mt++)
            #pragma unroll
            for (int nt = 0; nt < 4; nt++)
                mma_tf32(acc[mt][nt], af[mt], bf[nt]);
    }

    const float scale = 0.11180339887498949f;
    #pragma unroll
    for (int mt = 0; mt < 2; mt++) {
        const int r0 = i0 + wm + mt * 16 + g;
        const int r1 = r0 + 8;
        #pragma unroll
        for (int nt = 0; nt < 4; nt++) {
            const int c = j0 + wn + nt * 8 + 2 * tig;
            if (c < Tk)     { sb[(size_t)r0 * Tpad + c]     = acc[mt][nt][0] * scale;
                              sb[(size_t)r1 * Tpad + c]     = acc[mt][nt][2] * scale; }
            if (c + 1 < Tk) { sb[(size_t)r0 * Tpad + c + 1] = acc[mt][nt][1] * scale;
                              sb[(size_t)r1 * Tpad + c + 1] = acc[mt][nt][3] * scale; }
        }
    }
}

// ---------------- softmax (padded) ----------------
__global__ void softmax_kernel(float* __restrict__ S, int rows, int L, int Lpad)
{
    const int w = (blockIdx.x << 3) + (threadIdx.x >> 5);
    if (w >= rows) return;
    const int lane = threadIdx.x & 31;
    float* row = S + (size_t)w * Lpad;
    float v[32];
    float m = -3.4e38f;
    #pragma unroll
    for (int p = 0; p < 32; p++) {
        const int i = lane + (p << 5);
        v[p] = (i < L) ? row[i] : -3.4e38f;
        m = fmaxf(m, v[p]);
    }
    #pragma unroll
    for (int o = 16; o > 0; o >>= 1) m = fmaxf(m, __shfl_xor_sync(0xffffffffu, m, o));
    float s = 0.f;
    #pragma unroll
    for (int p = 0; p < 32; p++) {
        const int i = lane + (p << 5);
        if (i < L) { v[p] = __expf(v[p] - m); s += v[p]; }
    }
    #pragma unroll
    for (int o = 16; o > 0; o >>= 1) s += __shfl_xor_sync(0xffffffffu, s, o);
    const float inv = 1.f / s;
    #pragma unroll
    for (int p = 0; p < 32; p++) {
        const int i = lane + (p << 5);
        if (i < L) row[i] = v[p] * inv;
        else if (i < Lpad) row[i] = 0.f;
    }
}

// ---------------- MMA attention PV ----------------
// block: 128 rows x 80 cols, 8 warps (4x2), warp tile 32x40.
#define PP 36   // Ps pitch
#define VP 88   // Vs pitch: bank mult on tig = 24 -> conflict-free
__global__ __launch_bounds__(256)
void attn_pv_mma(const float* __restrict__ P, const float* __restrict__ V,
                 float* __restrict__ O, int Tk, int Tpad, int vSeq)
{
    __shared__ float Ps[128 * PP];
    __shared__ float Vs[32 * VP];
    const int bh = blockIdx.z, b = bh >> 3, n = bh & 7;
    const float* pb = P + (size_t)bh * Sq * Tpad;
    const float* vb = V + (size_t)b * vSeq * Cdim + n * HSZ;
    float* ob = O + (size_t)b * Sq * Cdim + n * HSZ;
    const int i0 = blockIdx.x * 128;
    const int tid = threadIdx.x;
    const int lane = tid & 31, warp = tid >> 5;
    const int g = lane >> 2, tig = lane & 3;
    const int wm = (warp >> 1) * 32, wn = (warp & 1) * 40;

    const int pr = tid >> 1, pc = (tid & 1) * 16;

    float acc[2][5][4];
    #pragma unroll
    for (int mt = 0; mt < 2; mt++)
        #pragma unroll
        for (int nt = 0; nt < 5; nt++)
            #pragma unroll
            for (int i = 0; i < 4; i++) acc[mt][nt][i] = 0.f;

    for (int t0 = 0; t0 < Tpad; t0 += 32) {
        #pragma unroll
        for (int l = 0; l < 4; l++) {
            const float4 pv = *reinterpret_cast<const float4*>(
                pb + (size_t)(i0 + pr) * Tpad + t0 + pc + l * 4);
            *reinterpret_cast<float4*>(&Ps[pr * PP + pc + l * 4]) = pv;
        }
        for (int e = tid; e < 32 * 20; e += 256) {
            const int kr = e / 20, c = (e % 20) * 4;
            float4 vv = make_float4(0.f, 0.f, 0.f, 0.f);
            if (t0 + kr < Tk)
                vv = *reinterpret_cast<const float4*>(vb + (size_t)(t0 + kr) * Cdim + c);
            *reinterpret_cast<float4*>(&Vs[kr * VP + c]) = vv;
        }
        __syncthreads();

        #pragma unroll
        for (int ks = 0; ks < 4; ks++) {
            const int kq = ks * 8 + tig;
            uint32_t af[2][4];
            #pragma unroll
            for (int mt = 0; mt < 2; mt++) {
                const int m = wm + mt * 16 + g;
                af[mt][0] = fu(Ps[m * PP + kq]);
                af[mt][1] = fu(Ps[(m + 8) * PP + kq]);
                af[mt][2] = fu(Ps[m * PP + kq + 4]);
                af[mt][3] = fu(Ps[(m + 8) * PP + kq + 4]);
            }
            uint32_t bf[5][2];
            #pragma unroll
            for (int nt = 0; nt < 5; nt++) {
                const int nn = wn + nt * 8 + g;
                bf[nt][0] = fu(Vs[kq * VP + nn]);
                bf[nt][1] = fu(Vs[(kq + 4) * VP + nn]);
            }
            #pragma unroll
            for (int mt = 0; mt < 2; mt++)
                #pragma unroll
                for (int nt = 0; nt < 5; nt++)
                    mma_tf32(acc[mt][nt], af[mt], bf[nt]);
        }
        __syncthreads();
    }

    #pragma unroll
    for (int mt = 0; mt < 2; mt++) {
        const int r0 = i0 + wm + mt * 16 + g;
        const int r1 = r0 + 8;
        #pragma unroll
        for (int nt = 0; nt < 5; nt++) {
            const int c = wn + nt * 8 + 2 * tig;
            *reinterpret_cast<float2*>(ob + (size_t)r0 * Cdim + c) =
                make_float2(acc[mt][nt][0], acc[mt][nt][1]);
            *reinterpret_cast<float2*>(ob + (size_t)r1 * Cdim + c) =
                make_float2(acc[mt][nt][2], acc[mt][nt][3]);
        }
    }
}

// ---------------- GEGLU ----------------
__device__ __forceinline__ float geglu_one(float xh, float g)
{
    const float t = tanhf(g * 0.7978845608f * (1.f + 0.044715f * g * g));
    return xh * 0.5f * g * (1.f + t);
}

__global__ void geglu_kernel(const float* __restrict__ ff, float* __restrict__ out)
{
    const size_t idx = (size_t)blockIdx.x * blockDim.x + threadIdx.x;
    if (idx >= (size_t)Mrows * (FFH / 4)) return;
    const size_t row = idx / (FFH / 4);
    const int c4 = (int)(idx % (FFH / 4));
    const float4 xh = *reinterpret_cast<const float4*>(ff + row * FFD + c4 * 4);
    const float4 gt = *reinterpret_cast<const float4*>(ff + row * FFD + FFH + c4 * 4);
    float4 o;
    o.x = geglu_one(xh.x, gt.x);
    o.y = geglu_one(xh.y, gt.y);
    o.z = geglu_one(xh.z, gt.z);
    o.w = geglu_one(xh.w, gt.w);
    *reinterpret_cast<float4*>(out + row * FFH + c4 * 4) = o;
}

// ---------------- host orchestration ----------------
extern "C" void kernel_launch(void* const* d_in, const int* in_sizes, int n_in,
                              void* d_out, int out_size)
{
    (void)in_sizes; (void)n_in; (void)out_size;
    const float* x     = (const float*)d_in[0];
    const float* ctx   = (const float*)d_in[1];
    const float* gn_g  = (const float*)d_in[2];
    const float* gn_b  = (const float*)d_in[3];
    const float* piw   = (const float*)d_in[4];
    const float* pib   = (const float*)d_in[5];
    const float* ln1g  = (const float*)d_in[6];
    const float* ln1b  = (const float*)d_in[7];
    const float* a1q   = (const float*)d_in[8];
    const float* a1k   = (const float*)d_in[9];
    const float* a1v   = (const float*)d_in[10];
    const float* a1o   = (const float*)d_in[11];
    const float* a1ob  = (const float*)d_in[12];
    const float* ln2g  = (const float*)d_in[13];
    const float* ln2b  = (const float*)d_in[14];
    const float* a2q   = (const float*)d_in[15];
    const float* a2k   = (const float*)d_in[16];
    const float* a2v   = (const float*)d_in[17];
    const float* a2o   = (const float*)d_in[18];
    const float* a2ob  = (const float*)d_in[19];
    const float* ln3g  = (const float*)d_in[20];
    const float* ln3b  = (const float*)d_in[21];
    const float* ff1w  = (const float*)d_in[22];
    const float* ff1b  = (const float*)d_in[23];
    const float* ff2w  = (const float*)d_in[24];
    const float* ff2b  = (const float*)d_in[25];
    const float* prw   = (const float*)d_in[26];
    const float* prb   = (const float*)d_in[27];
    float* out = (float*)d_out;

    float *ln, *y, *q, *k, *v, *at, *t, *sc, *ff, *gg;
    cudaGetSymbolAddress((void**)&ln, g_ln);
    cudaGetSymbolAddress((void**)&y,  g_y);
    cudaGetSymbolAddress((void**)&q,  g_q);
    cudaGetSymbolAddress((void**)&k,  g_k);
    cudaGetSymbolAddress((void**)&v,  g_v);
    cudaGetSymbolAddress((void**)&at, g_at);
    cudaGetSymbolAddress((void**)&t,  g_t);
    cudaGetSymbolAddress((void**)&sc, g_sc);
    cudaGetSymbolAddress((void**)&ff, g_ff);
    cudaGetSymbolAddress((void**)&gg, g_gg);

    cudaFuncSetAttribute(tf32_gemm_kernel,
                         cudaFuncAttributeMaxDynamicSharedMemorySize, GEMM_SMEM);

    const dim3 gemm640(Cdim / 128, Mrows / 128);
    const dim3 gemmCtx(Cdim / 128, (MCTX + 127) / 128);
    const dim3 gemmFF(FFD / 128, Mrows / 128);

    // y = proj_in(group_norm(x))
    groupnorm_kernel<<<Bn * 32, 256>>>(x, gn_g, gn_b, ln);
    tf32_gemm_kernel<<<gemm640, 256, GEMM_SMEM>>>(ln, piw, pib, nullptr, y, Mrows, Cdim, Cdim);

    // self attention
    layernorm_kernel<<<Mrows / 8, 256>>>(y, ln1g, ln1b, ln, Mrows);
    tf32_gemm_kernel<<<gemm640, 256, GEMM_SMEM>>>(ln, a1q, nullptr, nullptr, q, Mrows, Cdim, Cdim);
    tf32_gemm_kernel<<<gemm640, 256, GEMM_SMEM>>>(ln, a1k, nullptr, nullptr, k, Mrows, Cdim, Cdim);
    tf32_gemm_kernel<<<gemm640, 256, GEMM_SMEM>>>(ln, a1v, nullptr, nullptr, v, Mrows, Cdim, Cdim);
    attn_scores_mma<<<dim3(16, 16, 64), 128>>>(q, k, sc, Sq, Sq, Sq);
    softmax_kernel<<<(64 * Sq) / 8, 256>>>(sc, 64 * Sq, Sq, Sq);
    attn_pv_mma<<<dim3(8, 1, 64), 256>>>(sc, v, at, Sq, Sq, Sq);
    tf32_gemm_kernel<<<gemm640, 256, GEMM_SMEM>>>(at, a1o, a1ob, y, t, Mrows, Cdim, Cdim);

    // cross attention
    layernorm_kernel<<<Mrows / 8, 256>>>(t, ln2g, ln2b, ln, Mrows);
    tf32_gemm_kernel<<<gemmCtx, 256, GEMM_SMEM>>>(ctx, a2k, nullptr, nullptr, k, MCTX, Cdim, CTXD);
    tf32_gemm_kernel<<<gemmCtx, 256, GEMM_SMEM>>>(ctx, a2v, nullptr, nullptr, v, MCTX, Cdim, CTXD);
    tf32_gemm_kernel<<<gemm640, 256, GEMM_SMEM>>>(ln, a2q, nullptr, nullptr, q, Mrows, Cdim, Cdim);
    attn_scores_mma<<<dim3(2, 16, 64), 128>>>(q, k, sc, Tctx, TPAD, Tctx);
    softmax_kernel<<<(64 * Sq) / 8, 256>>>(sc, 64 * Sq, Tctx, TPAD);
    attn_pv_mma<<<dim3(8, 1, 64), 256>>>(sc, v, at, Tctx, TPAD, Tctx);
    tf32_gemm_kernel<<<gemm640, 256, GEMM_SMEM>>>(at, a2o, a2ob, t, t, Mrows, Cdim, Cdim);

    // GEGLU feed-forward
    layernorm_kernel<<<Mrows / 8, 256>>>(t, ln3g, ln3b, ln, Mrows);
    tf32_gemm_kernel<<<gemmFF, 256, GEMM_SMEM>>>(ln, ff1w, ff1b, nullptr, ff, Mrows, FFD, Cdim);
    geglu_kernel<<<(Mrows * (FFH / 4)) / 256, 256>>>(ff, gg);
    tf32_gemm_kernel<<<gemm640, 256, GEMM_SMEM>>>(gg, ff2w, ff2b, t, t, Mrows, Cdim, FFH);

    // proj_out + input residual
    tf32_gemm_kernel<<<gemm640, 256, GEMM_SMEM>>>(t, prw, prb, x, out, Mrows, Cdim, Cdim);
}